// round 15
// baseline (speedup 1.0000x reference)
#include <cuda_runtime.h>
#include <math.h>
#include <stdint.h>

#define NMAX 100000
#define KK   27

__device__ float g_h0[NMAX * 32];
__device__ float g_h1[NMAX * 128];
__device__ float g_W1t[KK * 128 * 32];   // [k][n=128][c=32]  (col-major B)
__device__ float g_W2t[KK * 32 * 128];   // [k][n=32][c=128]
__device__ int   g_mask_w4;

// ---------------- helpers ----------------
__device__ __forceinline__ uint32_t smem_u32(const void* p) {
    uint32_t a;
    asm("{ .reg .u64 t; cvta.to.shared.u64 t, %1; cvt.u32.u64 %0, t; }" : "=r"(a) : "l"(p));
    return a;
}
__device__ __forceinline__ float gelu_f(float v) {
    return 0.5f * v * (1.0f + erff(v * 0.70710678118654752f));
}
__device__ __forceinline__ float to_tf32(float v) {
    uint32_t r; asm("cvt.rna.tf32.f32 %0, %1;" : "=r"(r) : "f"(v));
    return __uint_as_float(r);
}
__device__ __forceinline__ int mask_at(const void* m, int off, int w4) {
    if (w4) return ((const int*)m)[off];
    return (int)((const unsigned char*)m)[off];
}
__device__ __forceinline__ void cp16(uint32_t dst, const void* src, unsigned srcsz) {
    asm volatile("cp.async.cg.shared.global [%0], [%1], 16, %2;"
                 :: "r"(dst), "l"(src), "r"(srcsz) : "memory");
}
#define CP_COMMIT() asm volatile("cp.async.commit_group;" ::: "memory")
#define CP_WAIT0()  asm volatile("cp.async.wait_group 0;" ::: "memory")
#define CP_WAIT1()  asm volatile("cp.async.wait_group 1;" ::: "memory")
#define CP_WAIT2()  asm volatile("cp.async.wait_group 2;" ::: "memory")
#define CP_WAIT_FOR(kk, NIT) do { \
    if ((kk) + 2 < (NIT)) CP_WAIT2(); \
    else if ((kk) + 1 < (NIT)) CP_WAIT1(); \
    else CP_WAIT0(); } while (0)

// m16n8k8 tf32 mma
__device__ __forceinline__ void mma8(float* c, const uint32_t* a, uint32_t b0, uint32_t b1) {
    asm volatile(
        "mma.sync.aligned.m16n8k8.row.col.f32.tf32.tf32.f32 "
        "{%0,%1,%2,%3}, {%4,%5,%6,%7}, {%8,%9}, {%0,%1,%2,%3};"
        : "+f"(c[0]), "+f"(c[1]), "+f"(c[2]), "+f"(c[3])
        : "r"(a[0]), "r"(a[1]), "r"(a[2]), "r"(a[3]), "r"(b0), "r"(b1));
}

// ---------------- prep: weight transpose + tf32 rounding ----------------
__global__ void k_prep(const float* __restrict__ W1, const float* __restrict__ W2) {
    int t = blockIdx.x * 256 + threadIdx.x;
    if (t < KK * 4096) {
        int k = t >> 12, r = t & 4095;
        g_W1t[k * 4096 + (r & 127) * 32 + (r >> 7)] = to_tf32(W1[t]);
        g_W2t[k * 4096 + (r & 31) * 128 + (r >> 5)] = to_tf32(W2[t]);
    }
}

// ---------------- conv0 (SIMT fp32) ----------------
__global__ void k_conv0(const float* __restrict__ x, const float* __restrict__ Wc,
                        const float* __restrict__ g0, const float* __restrict__ b0,
                        const unsigned char* __restrict__ maskraw, int n) {
    __shared__ float sW[1024];
    int tid = threadIdx.x;
    if (blockIdx.x == 0 && tid == 0) {
        int w4 = 1;
        for (int t = 1; t < 400; ++t)
            if ((t & 3) != 0 && maskraw[t] != 0) { w4 = 0; break; }
        g_mask_w4 = w4;
    }
    for (int i = tid; i < 1024; i += 256) sW[i] = Wc[i];
    __syncthreads();

    int lane = tid & 31, w = tid >> 5;
    int row = blockIdx.x * 8 + w;
    if (row >= n) return;
    float xv = x[row * 32 + lane];
    float acc = 0.0f;
#pragma unroll
    for (int c = 0; c < 32; ++c) {
        float xs = __shfl_sync(0xffffffffu, xv, c);
        acc = fmaf(xs, sW[c * 32 + lane], acc);
    }
    float s = acc;
#pragma unroll
    for (int o = 16; o > 0; o >>= 1) s += __shfl_xor_sync(0xffffffffu, s, o);
    float mu = s * (1.0f / 32.0f);
    float d = acc - mu;
    float q = d * d;
#pragma unroll
    for (int o = 16; o > 0; o >>= 1) q += __shfl_xor_sync(0xffffffffu, q, o);
    float y = d * rsqrtf(q * (1.0f / 32.0f) + 1e-6f) * g0[lane] + b0[lane];
    g_h0[row * 32 + lane] = to_tf32(gelu_f(y));
}

// ---------------- conv1: 128x128, K=16 chunks x 54, depth-4 ----------------
// A[s][128][20]f, B[s][128][20]f; offset table uint32 [27][128]
#define T1_A(s)  ((s) * 10240)
#define T1_B(s)  (40960 + (s) * 10240)
#define T1_OFF   81920
#define T1_G     95744
#define T1_BETA  96256
#define T1_RS    96768
#define T1_RQ    97792
#define T1_MU    98816
#define T1_SIG   99328
#define T1_SMEM  99840

__device__ __forceinline__ void fill1(uint32_t sb, const uint32_t* toff, int kk,
                                      int st, int tid) {
    int k = kk >> 1, h = kk & 1;
#pragma unroll
    for (int i = 0; i < 2; i++) {           // A: 512 chunks
        int c = tid + i * 256;
        int row = c >> 2, j = c & 3;
        uint32_t off = toff[k * 128 + row];
        unsigned sz = (off == 0xFFFFFFFFu) ? 0u : 16u;
        uint32_t ob = (off == 0xFFFFFFFFu) ? 0u : off;
        const char* src = (const char*)g_h0 + ob + h * 64 + j * 16;
        cp16(sb + T1_A(st) + row * 80 + j * 16, src, sz);
    }
    const char* wsrc = (const char*)g_W1t + (size_t)k * 16384 + h * 64;
#pragma unroll
    for (int i = 0; i < 2; i++) {           // B: 512 chunks
        int c = tid + i * 256;
        int nr = c >> 2, j = c & 3;
        cp16(sb + T1_B(st) + nr * 80 + j * 16, wsrc + nr * 128 + j * 16, 16);
    }
}

__global__ void __launch_bounds__(256, 2)
k_conv1(const int* __restrict__ nidx, const void* __restrict__ nmask,
        const float* __restrict__ g1v, const float* __restrict__ b1v, int n) {
    extern __shared__ char dyn[];
    uint32_t sb = smem_u32(dyn);
    int tid = threadIdx.x, wid = tid >> 5, lane = tid & 31;
    int g = lane >> 2, t4 = lane & 3;
    int row0 = blockIdx.x * 128;
    uint32_t* toff = (uint32_t*)(dyn + T1_OFF);
    float* sg  = (float*)(dyn + T1_G);
    float* sbe = (float*)(dyn + T1_BETA);

    if (tid < 128) { sg[tid] = g1v[tid]; sbe[tid] = b1v[tid]; }
    int w4 = g_mask_w4;
    for (int t = tid; t < KK * 128; t += 256) {
        int m = t / KK, k = t % KK;
        int nr = row0 + m; uint32_t off = 0xFFFFFFFFu;
        if (nr < n) {
            int o = nr * KK + k;
            if (mask_at(nmask, o, w4)) off = (uint32_t)nidx[o] * 128u;
        }
        toff[k * 128 + m] = off;
    }
    __syncthreads();

    const int NIT = KK * 2;                  // 54 K=16 chunks
    fill1(sb, toff, 0, 0, tid); CP_COMMIT();
    fill1(sb, toff, 1, 1, tid); CP_COMMIT();
    fill1(sb, toff, 2, 2, tid); CP_COMMIT();

    int mw = wid & 3, nw = wid >> 2;
    int mbase = mw * 32, nbase = nw * 64;
    float acc[2][8][4];
#pragma unroll
    for (int mt = 0; mt < 2; mt++)
#pragma unroll
        for (int nt = 0; nt < 8; nt++)
#pragma unroll
            for (int j = 0; j < 4; j++) acc[mt][nt][j] = 0.f;

    for (int kk = 0; kk < NIT; kk++) {
        int b = kk & 3;
        CP_WAIT_FOR(kk, NIT);
        __syncthreads();
        const uint32_t* A = (const uint32_t*)(dyn + T1_A(b));
        const uint32_t* B = (const uint32_t*)(dyn + T1_B(b));
#pragma unroll
        for (int kt = 0; kt < 2; kt++) {
            int kb = kt * 8;
            uint32_t a[2][4];
#pragma unroll
            for (int mt = 0; mt < 2; mt++) {
                int r = mbase + mt * 16 + g;
                a[mt][0] = A[r * 20 + kb + t4];
                a[mt][1] = A[(r + 8) * 20 + kb + t4];
                a[mt][2] = A[r * 20 + kb + t4 + 4];
                a[mt][3] = A[(r + 8) * 20 + kb + t4 + 4];
            }
#pragma unroll
            for (int nt = 0; nt < 8; nt++) {
                int cn = (nbase + nt * 8 + g) * 20 + kb + t4;
                uint32_t b0 = B[cn], b1 = B[cn + 4];
                mma8(acc[0][nt], a[0], b0, b1);
                mma8(acc[1][nt], a[1], b0, b1);
            }
        }
        if (kk + 3 < NIT) { fill1(sb, toff, kk + 3, (kk + 3) & 3, tid); CP_COMMIT(); }
    }
    __syncthreads();

    // ---- fused LN(128) + GELU epilogue ----
    float* rs_ = (float*)(dyn + T1_RS);
    float* rq_ = (float*)(dyn + T1_RQ);
#pragma unroll
    for (int mt = 0; mt < 2; mt++)
#pragma unroll
        for (int rr = 0; rr < 2; rr++) {
            float s = 0.f, q = 0.f;
#pragma unroll
            for (int nt = 0; nt < 8; nt++) {
                float v0 = acc[mt][nt][rr * 2], v1 = acc[mt][nt][rr * 2 + 1];
                s += v0 + v1; q += v0 * v0 + v1 * v1;
            }
            s += __shfl_xor_sync(0xffffffffu, s, 1);
            s += __shfl_xor_sync(0xffffffffu, s, 2);
            q += __shfl_xor_sync(0xffffffffu, q, 1);
            q += __shfl_xor_sync(0xffffffffu, q, 2);
            if (t4 == 0) {
                int r = mbase + mt * 16 + rr * 8 + g;
                rs_[r * 2 + nw] = s; rq_[r * 2 + nw] = q;
            }
        }
    __syncthreads();
    float* smu = (float*)(dyn + T1_MU);
    float* ssg = (float*)(dyn + T1_SIG);
    if (tid < 128) {
        float s = rs_[tid * 2] + rs_[tid * 2 + 1];
        float q = rq_[tid * 2] + rq_[tid * 2 + 1];
        float mu = s * (1.0f / 128.0f);
        smu[tid] = mu;
        ssg[tid] = rsqrtf(q * (1.0f / 128.0f) - mu * mu + 1e-6f);
    }
    __syncthreads();
#pragma unroll
    for (int mt = 0; mt < 2; mt++)
#pragma unroll
        for (int rr = 0; rr < 2; rr++) {
            int r = mbase + mt * 16 + rr * 8 + g;
            int nr = row0 + r;
            if (nr >= n) continue;
            float mu = smu[r], rs = ssg[r];
            float* dst = g_h1 + (size_t)nr * 128;
#pragma unroll
            for (int nt = 0; nt < 8; nt++) {
                int c = nbase + nt * 8 + t4 * 2;
                float y0 = to_tf32(gelu_f((acc[mt][nt][rr * 2]     - mu) * rs * sg[c]     + sbe[c]));
                float y1 = to_tf32(gelu_f((acc[mt][nt][rr * 2 + 1] - mu) * rs * sg[c + 1] + sbe[c + 1]));
                *(float2*)(dst + c) = make_float2(y0, y1);
            }
        }
}

// ---------------- conv2: 128x32, K=16 stages x 216, depth-6, pair-sync ----------------
// Stage: A[128][20]f (10240B) + B[32][20]f (2560B) = 12800B. 6 stages.
#define U2_STG   12800
#define U2_A(s)  ((s) * U2_STG)
#define U2_B(s)  ((s) * U2_STG + 10240)
#define U2_OFF   76800
#define U2_G     90624
#define U2_BETA  90752
#define U2_SMEM  91136

__device__ __forceinline__ void fill2(uint32_t sb, const uint32_t* toff, int kk,
                                      int st, int tid) {
    int k = kk >> 3, q = kk & 7;             // kernel offset k, K=16 chunk q (q*64B)
#pragma unroll
    for (int i = 0; i < 2; i++) {            // A: 512 chunks of 16B
        int c = tid + i * 256;
        int row = c >> 2, j = c & 3;
        uint32_t off = toff[k * 128 + row];
        unsigned sz = (off == 0xFFFFFFFFu) ? 0u : 16u;
        uint32_t ob = (off == 0xFFFFFFFFu) ? 0u : off;
        const char* src = (const char*)g_h1 + ob + q * 64 + j * 16;
        cp16(sb + U2_A(st) + row * 80 + j * 16, src, sz);
    }
    if (tid < 128) {                         // B: 128 chunks (32 rows x 64B)
        int nr = tid >> 2, j = tid & 3;
        const char* src = (const char*)g_W2t + (size_t)k * 16384 + nr * 512 + q * 64 + j * 16;
        cp16(sb + U2_B(st) + nr * 80 + j * 16, src, 16);
    }
}

__global__ void __launch_bounds__(256, 2)
k_conv2(const float* __restrict__ x, const int* __restrict__ nidx,
        const void* __restrict__ nmask, const float* __restrict__ g2v,
        const float* __restrict__ b2v, float* __restrict__ out, int n) {
    extern __shared__ char dyn[];
    uint32_t sb = smem_u32(dyn);
    int tid = threadIdx.x, wid = tid >> 5, lane = tid & 31;
    int g = lane >> 2, t4 = lane & 3;
    int row0 = blockIdx.x * 128;
    uint32_t* toff = (uint32_t*)(dyn + U2_OFF);
    float* sg  = (float*)(dyn + U2_G);
    float* sbe = (float*)(dyn + U2_BETA);

    if (tid < 32) { sg[tid] = g2v[tid]; sbe[tid] = b2v[tid]; }
    int w4 = g_mask_w4;
    for (int t = tid; t < KK * 128; t += 256) {
        int m = t / KK, k = t % KK;
        int nr = row0 + m; uint32_t off = 0xFFFFFFFFu;
        if (nr < n) {
            int o = nr * KK + k;
            if (mask_at(nmask, o, w4)) off = (uint32_t)nidx[o] * 512u;
        }
        toff[k * 128 + m] = off;
    }
    __syncthreads();

    const int NIT = KK * 8;                  // 216 K=16 stages (8 per kernel offset)
    fill2(sb, toff, 0, 0, tid); CP_COMMIT();
    fill2(sb, toff, 1, 1, tid); CP_COMMIT();
    fill2(sb, toff, 2, 2, tid); CP_COMMIT();
    fill2(sb, toff, 3, 3, tid); CP_COMMIT();

    int mw = wid & 3, kh = wid >> 2;         // 4 m-warps x 2 k-halves (of K=16)
    int mbase = mw * 32, kb = kh * 8;
    float acc[2][4][4];
#pragma unroll
    for (int mt = 0; mt < 2; mt++)
#pragma unroll
        for (int nt = 0; nt < 4; nt++)
#pragma unroll
            for (int j = 0; j < 4; j++) acc[mt][nt][j] = 0.f;

    int st = 0;                              // ring stage of iter kk
    for (int kk = 0; kk < NIT; kk += 2) {
        if (kk + 4 < NIT) CP_WAIT2(); else CP_WAIT0();
        __syncthreads();
#pragma unroll
        for (int half = 0; half < 2; half++) {
            int s = st + half; if (s >= 6) s -= 6;
            const uint32_t* A = (const uint32_t*)(dyn + U2_A(s));
            const uint32_t* B = (const uint32_t*)(dyn + U2_B(s));
            uint32_t a[2][4];
#pragma unroll
            for (int mt = 0; mt < 2; mt++) {
                int r = mbase + mt * 16 + g;
                a[mt][0] = A[r * 20 + kb + t4];
                a[mt][1] = A[(r + 8) * 20 + kb + t4];
                a[mt][2] = A[r * 20 + kb + t4 + 4];
                a[mt][3] = A[(r + 8) * 20 + kb + t4 + 4];
            }
#pragma unroll
            for (int nt = 0; nt < 4; nt++) {
                int cn = (nt * 8 + g) * 20 + kb + t4;
                uint32_t b0 = B[cn], b1 = B[cn + 4];
                mma8(acc[0][nt], a[0], b0, b1);
                mma8(acc[1][nt], a[1], b0, b1);
            }
        }
        if (kk + 4 < NIT) {
            int s4 = st + 4; if (s4 >= 6) s4 -= 6;
            fill2(sb, toff, kk + 4, s4, tid); CP_COMMIT();
            int s5 = st + 5; if (s5 >= 6) s5 -= 6;
            fill2(sb, toff, kk + 5, s5, tid); CP_COMMIT();
        }
        st += 2; if (st >= 6) st -= 6;
    }
    __syncthreads();

    // ---- k-half reduction via smem (reuse stage region), P[128][34] ----
    float* P = (float*)dyn;
    if (kh == 1) {
#pragma unroll
        for (int mt = 0; mt < 2; mt++)
#pragma unroll
            for (int nt = 0; nt < 4; nt++) {
                int r = mbase + mt * 16 + g, c = nt * 8 + t4 * 2;
                *(float2*)&P[r * 34 + c]       = make_float2(acc[mt][nt][0], acc[mt][nt][1]);
                *(float2*)&P[(r + 8) * 34 + c] = make_float2(acc[mt][nt][2], acc[mt][nt][3]);
            }
    }
    __syncthreads();
    if (kh == 0) {
#pragma unroll
        for (int mt = 0; mt < 2; mt++)
#pragma unroll
            for (int nt = 0; nt < 4; nt++) {
                int r = mbase + mt * 16 + g, c = nt * 8 + t4 * 2;
                float2 p0 = *(float2*)&P[r * 34 + c];
                float2 p1 = *(float2*)&P[(r + 8) * 34 + c];
                acc[mt][nt][0] += p0.x; acc[mt][nt][1] += p0.y;
                acc[mt][nt][2] += p1.x; acc[mt][nt][3] += p1.y;
            }
        // ---- fused LN(32) + residual + GELU ----
#pragma unroll
        for (int mt = 0; mt < 2; mt++)
#pragma unroll
            for (int rr = 0; rr < 2; rr++) {
                float s = 0.f, q = 0.f;
#pragma unroll
                for (int nt = 0; nt < 4; nt++) {
                    float v0 = acc[mt][nt][rr * 2], v1 = acc[mt][nt][rr * 2 + 1];
                    s += v0 + v1; q += v0 * v0 + v1 * v1;
                }
                s += __shfl_xor_sync(0xffffffffu, s, 1);
                s += __shfl_xor_sync(0xffffffffu, s, 2);
                q += __shfl_xor_sync(0xffffffffu, q, 1);
                q += __shfl_xor_sync(0xffffffffu, q, 2);
                float mu = s * (1.0f / 32.0f);
                float rs = rsqrtf(q * (1.0f / 32.0f) - mu * mu + 1e-6f);
                int r = mbase + mt * 16 + rr * 8 + g;
                int nr = row0 + r;
                if (nr >= n) continue;
#pragma unroll
                for (int nt = 0; nt < 4; nt++) {
                    int c = nt * 8 + t4 * 2;
                    float2 xv = *(const float2*)(x + (size_t)nr * 32 + c);
                    float y0 = gelu_f((acc[mt][nt][rr * 2]     - mu) * rs * sg[c]     + sbe[c]     + xv.x);
                    float y1 = gelu_f((acc[mt][nt][rr * 2 + 1] - mu) * rs * sg[c + 1] + sbe[c + 1] + xv.y);
                    *(float2*)(out + (size_t)nr * 32 + c) = make_float2(y0, y1);
                }
            }
    }
}

// ---------------------------------------------------------------------------
extern "C" void kernel_launch(void* const* d_in, const int* in_sizes, int n_in,
                              void* d_out, int out_size) {
    const float* x   = (const float*)d_in[0];
    const int*   nid = (const int*)d_in[1];
    const void*  msk = (const void*)d_in[2];
    const float* Wc  = (const float*)d_in[3];
    const float* g0  = (const float*)d_in[4];
    const float* b0  = (const float*)d_in[5];
    const float* W1  = (const float*)d_in[6];
    const float* g1  = (const float*)d_in[7];
    const float* b1  = (const float*)d_in[8];
    const float* W2  = (const float*)d_in[9];
    const float* g2  = (const float*)d_in[10];
    const float* b2  = (const float*)d_in[11];
    float* out = (float*)d_out;
    int n = in_sizes[0] / 32;

    cudaFuncSetAttribute(k_conv1, cudaFuncAttributeMaxDynamicSharedMemorySize, T1_SMEM);
    cudaFuncSetAttribute(k_conv2, cudaFuncAttributeMaxDynamicSharedMemorySize, U2_SMEM);

    k_prep<<<(KK * 4096 + 255) / 256, 256>>>(W1, W2);
    k_conv0<<<(n + 7) / 8, 256>>>(x, Wc, g0, b0, (const unsigned char*)msk, n);
    int nb = (n + 127) / 128;
    k_conv1<<<nb, 256, T1_SMEM>>>(nid, msk, g1, b1, n);
    k_conv2<<<nb, 256, U2_SMEM>>>(x, nid, msk, g2, b2, out, n);
}

// round 17
// speedup vs baseline: 1.0525x; 1.0525x over previous
#include <cuda_runtime.h>
#include <math.h>
#include <stdint.h>

#define NMAX 100000
#define KK   27

__device__ float g_h0[NMAX * 32];
__device__ float g_h1[NMAX * 128];
__device__ float g_W1t[KK * 128 * 32];   // [k][n=128][c=32]  (col-major B)
__device__ float g_W2t[KK * 32 * 128];   // [k][n=32][c=128]
__device__ int   g_mask_w4;

// ---------------- helpers ----------------
__device__ __forceinline__ uint32_t smem_u32(const void* p) {
    uint32_t a;
    asm("{ .reg .u64 t; cvta.to.shared.u64 t, %1; cvt.u32.u64 %0, t; }" : "=r"(a) : "l"(p));
    return a;
}
__device__ __forceinline__ float gelu_f(float v) {
    return 0.5f * v * (1.0f + erff(v * 0.70710678118654752f));
}
__device__ __forceinline__ float to_tf32(float v) {
    uint32_t r; asm("cvt.rna.tf32.f32 %0, %1;" : "=r"(r) : "f"(v));
    return __uint_as_float(r);
}
__device__ __forceinline__ int mask_at(const void* m, int off, int w4) {
    if (w4) return ((const int*)m)[off];
    return (int)((const unsigned char*)m)[off];
}
__device__ __forceinline__ void cp16(uint32_t dst, const void* src, unsigned srcsz) {
    asm volatile("cp.async.cg.shared.global [%0], [%1], 16, %2;"
                 :: "r"(dst), "l"(src), "r"(srcsz) : "memory");
}
#define CP_COMMIT() asm volatile("cp.async.commit_group;" ::: "memory")
#define CP_WAIT0()  asm volatile("cp.async.wait_group 0;" ::: "memory")
#define CP_WAIT1()  asm volatile("cp.async.wait_group 1;" ::: "memory")
#define CP_WAIT2()  asm volatile("cp.async.wait_group 2;" ::: "memory")
#define CP_WAIT_FOR(kk, NIT) do { \
    if ((kk) + 2 < (NIT)) CP_WAIT2(); \
    else if ((kk) + 1 < (NIT)) CP_WAIT1(); \
    else CP_WAIT0(); } while (0)

// m16n8k8 tf32 mma
__device__ __forceinline__ void mma8(float* c, const uint32_t* a, uint32_t b0, uint32_t b1) {
    asm volatile(
        "mma.sync.aligned.m16n8k8.row.col.f32.tf32.tf32.f32 "
        "{%0,%1,%2,%3}, {%4,%5,%6,%7}, {%8,%9}, {%0,%1,%2,%3};"
        : "+f"(c[0]), "+f"(c[1]), "+f"(c[2]), "+f"(c[3])
        : "r"(a[0]), "r"(a[1]), "r"(a[2]), "r"(a[3]), "r"(b0), "r"(b1));
}

// ---------------- prep: weight transpose + tf32 rounding ----------------
__global__ void k_prep(const float* __restrict__ W1, const float* __restrict__ W2) {
    int t = blockIdx.x * 256 + threadIdx.x;
    if (t < KK * 4096) {
        int k = t >> 12, r = t & 4095;
        g_W1t[k * 4096 + (r & 127) * 32 + (r >> 7)] = to_tf32(W1[t]);
        g_W2t[k * 4096 + (r & 31) * 128 + (r >> 5)] = to_tf32(W2[t]);
    }
}

// ---------------- conv0 (SIMT fp32) ----------------
__global__ void k_conv0(const float* __restrict__ x, const float* __restrict__ Wc,
                        const float* __restrict__ g0, const float* __restrict__ b0,
                        const unsigned char* __restrict__ maskraw, int n) {
    __shared__ float sW[1024];
    int tid = threadIdx.x;
    if (blockIdx.x == 0 && tid == 0) {
        int w4 = 1;
        for (int t = 1; t < 400; ++t)
            if ((t & 3) != 0 && maskraw[t] != 0) { w4 = 0; break; }
        g_mask_w4 = w4;
    }
    for (int i = tid; i < 1024; i += 256) sW[i] = Wc[i];
    __syncthreads();

    int lane = tid & 31, w = tid >> 5;
    int row = blockIdx.x * 8 + w;
    if (row >= n) return;
    float xv = x[row * 32 + lane];
    float acc = 0.0f;
#pragma unroll
    for (int c = 0; c < 32; ++c) {
        float xs = __shfl_sync(0xffffffffu, xv, c);
        acc = fmaf(xs, sW[c * 32 + lane], acc);
    }
    float s = acc;
#pragma unroll
    for (int o = 16; o > 0; o >>= 1) s += __shfl_xor_sync(0xffffffffu, s, o);
    float mu = s * (1.0f / 32.0f);
    float d = acc - mu;
    float q = d * d;
#pragma unroll
    for (int o = 16; o > 0; o >>= 1) q += __shfl_xor_sync(0xffffffffu, q, o);
    float y = d * rsqrtf(q * (1.0f / 32.0f) + 1e-6f) * g0[lane] + b0[lane];
    g_h0[row * 32 + lane] = to_tf32(gelu_f(y));
}

// ---------------- conv1: 128x128, K=16 chunks x 54, depth-4 ----------------
// A[s][128][20]f, B[s][128][20]f; offset table uint32 [27][128]
#define T1_A(s)  ((s) * 10240)
#define T1_B(s)  (40960 + (s) * 10240)
#define T1_OFF   81920
#define T1_G     95744
#define T1_BETA  96256
#define T1_RS    96768
#define T1_RQ    97792
#define T1_MU    98816
#define T1_SIG   99328
#define T1_SMEM  99840

__device__ __forceinline__ void fill1(uint32_t sb, const uint32_t* toff, int kk,
                                      int st, int tid) {
    int k = kk >> 1, h = kk & 1;
#pragma unroll
    for (int i = 0; i < 2; i++) {           // A: 512 chunks
        int c = tid + i * 256;
        int row = c >> 2, j = c & 3;
        uint32_t off = toff[k * 128 + row];
        unsigned sz = (off == 0xFFFFFFFFu) ? 0u : 16u;
        uint32_t ob = (off == 0xFFFFFFFFu) ? 0u : off;
        const char* src = (const char*)g_h0 + ob + h * 64 + j * 16;
        cp16(sb + T1_A(st) + row * 80 + j * 16, src, sz);
    }
    const char* wsrc = (const char*)g_W1t + (size_t)k * 16384 + h * 64;
#pragma unroll
    for (int i = 0; i < 2; i++) {           // B: 512 chunks
        int c = tid + i * 256;
        int nr = c >> 2, j = c & 3;
        cp16(sb + T1_B(st) + nr * 80 + j * 16, wsrc + nr * 128 + j * 16, 16);
    }
}

__global__ void __launch_bounds__(256, 2)
k_conv1(const int* __restrict__ nidx, const void* __restrict__ nmask,
        const float* __restrict__ g1v, const float* __restrict__ b1v, int n) {
    extern __shared__ char dyn[];
    uint32_t sb = smem_u32(dyn);
    int tid = threadIdx.x, wid = tid >> 5, lane = tid & 31;
    int g = lane >> 2, t4 = lane & 3;
    int row0 = blockIdx.x * 128;
    uint32_t* toff = (uint32_t*)(dyn + T1_OFF);
    float* sg  = (float*)(dyn + T1_G);
    float* sbe = (float*)(dyn + T1_BETA);

    if (tid < 128) { sg[tid] = g1v[tid]; sbe[tid] = b1v[tid]; }
    int w4 = g_mask_w4;
    for (int t = tid; t < KK * 128; t += 256) {
        int m = t / KK, k = t % KK;
        int nr = row0 + m; uint32_t off = 0xFFFFFFFFu;
        if (nr < n) {
            int o = nr * KK + k;
            if (mask_at(nmask, o, w4)) off = (uint32_t)nidx[o] * 128u;
        }
        toff[k * 128 + m] = off;
    }
    __syncthreads();

    const int NIT = KK * 2;                  // 54 K=16 chunks
    fill1(sb, toff, 0, 0, tid); CP_COMMIT();
    fill1(sb, toff, 1, 1, tid); CP_COMMIT();
    fill1(sb, toff, 2, 2, tid); CP_COMMIT();

    int mw = wid & 3, nw = wid >> 2;
    int mbase = mw * 32, nbase = nw * 64;
    float acc[2][8][4];
#pragma unroll
    for (int mt = 0; mt < 2; mt++)
#pragma unroll
        for (int nt = 0; nt < 8; nt++)
#pragma unroll
            for (int j = 0; j < 4; j++) acc[mt][nt][j] = 0.f;

    for (int kk = 0; kk < NIT; kk++) {
        int b = kk & 3;
        CP_WAIT_FOR(kk, NIT);
        __syncthreads();
        const uint32_t* A = (const uint32_t*)(dyn + T1_A(b));
        const uint32_t* B = (const uint32_t*)(dyn + T1_B(b));
#pragma unroll
        for (int kt = 0; kt < 2; kt++) {
            int kb = kt * 8;
            uint32_t a[2][4];
#pragma unroll
            for (int mt = 0; mt < 2; mt++) {
                int r = mbase + mt * 16 + g;
                a[mt][0] = A[r * 20 + kb + t4];
                a[mt][1] = A[(r + 8) * 20 + kb + t4];
                a[mt][2] = A[r * 20 + kb + t4 + 4];
                a[mt][3] = A[(r + 8) * 20 + kb + t4 + 4];
            }
#pragma unroll
            for (int nt = 0; nt < 8; nt++) {
                int cn = (nbase + nt * 8 + g) * 20 + kb + t4;
                uint32_t b0 = B[cn], b1 = B[cn + 4];
                mma8(acc[0][nt], a[0], b0, b1);
                mma8(acc[1][nt], a[1], b0, b1);
            }
        }
        if (kk + 3 < NIT) { fill1(sb, toff, kk + 3, (kk + 3) & 3, tid); CP_COMMIT(); }
    }
    __syncthreads();

    // ---- fused LN(128) + GELU epilogue ----
    float* rs_ = (float*)(dyn + T1_RS);
    float* rq_ = (float*)(dyn + T1_RQ);
#pragma unroll
    for (int mt = 0; mt < 2; mt++)
#pragma unroll
        for (int rr = 0; rr < 2; rr++) {
            float s = 0.f, q = 0.f;
#pragma unroll
            for (int nt = 0; nt < 8; nt++) {
                float v0 = acc[mt][nt][rr * 2], v1 = acc[mt][nt][rr * 2 + 1];
                s += v0 + v1; q += v0 * v0 + v1 * v1;
            }
            s += __shfl_xor_sync(0xffffffffu, s, 1);
            s += __shfl_xor_sync(0xffffffffu, s, 2);
            q += __shfl_xor_sync(0xffffffffu, q, 1);
            q += __shfl_xor_sync(0xffffffffu, q, 2);
            if (t4 == 0) {
                int r = mbase + mt * 16 + rr * 8 + g;
                rs_[r * 2 + nw] = s; rq_[r * 2 + nw] = q;
            }
        }
    __syncthreads();
    float* smu = (float*)(dyn + T1_MU);
    float* ssg = (float*)(dyn + T1_SIG);
    if (tid < 128) {
        float s = rs_[tid * 2] + rs_[tid * 2 + 1];
        float q = rq_[tid * 2] + rq_[tid * 2 + 1];
        float mu = s * (1.0f / 128.0f);
        smu[tid] = mu;
        ssg[tid] = rsqrtf(q * (1.0f / 128.0f) - mu * mu + 1e-6f);
    }
    __syncthreads();
#pragma unroll
    for (int mt = 0; mt < 2; mt++)
#pragma unroll
        for (int rr = 0; rr < 2; rr++) {
            int r = mbase + mt * 16 + rr * 8 + g;
            int nr = row0 + r;
            if (nr >= n) continue;
            float mu = smu[r], rs = ssg[r];
            float* dst = g_h1 + (size_t)nr * 128;
#pragma unroll
            for (int nt = 0; nt < 8; nt++) {
                int c = nbase + nt * 8 + t4 * 2;
                float y0 = to_tf32(gelu_f((acc[mt][nt][rr * 2]     - mu) * rs * sg[c]     + sbe[c]));
                float y1 = to_tf32(gelu_f((acc[mt][nt][rr * 2 + 1] - mu) * rs * sg[c + 1] + sbe[c + 1]));
                *(float2*)(dst + c) = make_float2(y0, y1);
            }
        }
}

// ---------------- conv2: 128x32, K=32 chunks x 108, depth-4 (R11 struct + off-table) ----
// A[s][128][36]f, B[s][32][36]f; offset table uint32 [27][128]
#define V2_A(s)  ((s) * 23040)
#define V2_B(s)  ((s) * 23040 + 18432)
#define V2_OFF   92160
#define V2_G     105984
#define V2_BETA  106112
#define V2_SMEM  106240

__device__ __forceinline__ void fill2(uint32_t sb, const uint32_t* toff, int kk,
                                      int st, int tid) {
    int k = kk >> 2, q = kk & 3;             // kernel offset k, K=32 chunk q (q*128B)
#pragma unroll
    for (int i = 0; i < 4; i++) {            // A: 1024 chunks of 16B
        int c = tid + i * 256;
        int row = c >> 3, j = c & 7;
        uint32_t off = toff[k * 128 + row];
        unsigned sz = (off == 0xFFFFFFFFu) ? 0u : 16u;
        uint32_t ob = (off == 0xFFFFFFFFu) ? 0u : off;
        const char* src = (const char*)g_h1 + ob + q * 128 + j * 16;
        cp16(sb + V2_A(st) + row * 144 + j * 16, src, sz);
    }
    {                                        // B: 256 chunks (32 rows x 128B)
        int nr = tid >> 3, j = tid & 7;
        const char* src = (const char*)g_W2t + (size_t)k * 16384 + nr * 512 + q * 128 + j * 16;
        cp16(sb + V2_B(st) + nr * 144 + j * 16, src, 16);
    }
}

__global__ void __launch_bounds__(256, 2)
k_conv2(const float* __restrict__ x, const int* __restrict__ nidx,
        const void* __restrict__ nmask, const float* __restrict__ g2v,
        const float* __restrict__ b2v, float* __restrict__ out, int n) {
    extern __shared__ char dyn[];
    uint32_t sb = smem_u32(dyn);
    int tid = threadIdx.x, wid = tid >> 5, lane = tid & 31;
    int g = lane >> 2, t4 = lane & 3;
    int row0 = blockIdx.x * 128;
    uint32_t* toff = (uint32_t*)(dyn + V2_OFF);
    float* sg  = (float*)(dyn + V2_G);
    float* sbe = (float*)(dyn + V2_BETA);

    if (tid < 32) { sg[tid] = g2v[tid]; sbe[tid] = b2v[tid]; }
    int w4 = g_mask_w4;
    for (int t = tid; t < KK * 128; t += 256) {
        int m = t / KK, k = t % KK;
        int nr = row0 + m; uint32_t off = 0xFFFFFFFFu;
        if (nr < n) {
            int o = nr * KK + k;
            if (mask_at(nmask, o, w4)) off = (uint32_t)nidx[o] * 512u;
        }
        toff[k * 128 + m] = off;
    }
    __syncthreads();

    const int NIT = KK * 4;                  // 108 K=32 chunks
    fill2(sb, toff, 0, 0, tid); CP_COMMIT();
    fill2(sb, toff, 1, 1, tid); CP_COMMIT();
    fill2(sb, toff, 2, 2, tid); CP_COMMIT();

    int mw = wid & 3, kh = wid >> 2;         // 4 m-warps x 2 k-halves
    int mbase = mw * 32, kqb = kh * 16;
    float acc[2][4][4];
#pragma unroll
    for (int mt = 0; mt < 2; mt++)
#pragma unroll
        for (int nt = 0; nt < 4; nt++)
#pragma unroll
            for (int j = 0; j < 4; j++) acc[mt][nt][j] = 0.f;

    for (int kk = 0; kk < NIT; kk++) {
        int b = kk & 3;
        CP_WAIT_FOR(kk, NIT);
        __syncthreads();
        const uint32_t* A = (const uint32_t*)(dyn + V2_A(b));
        const uint32_t* B = (const uint32_t*)(dyn + V2_B(b));
#pragma unroll
        for (int kt = 0; kt < 2; kt++) {
            int kb = kqb + kt * 8;
            uint32_t a[2][4];
#pragma unroll
            for (int mt = 0; mt < 2; mt++) {
                int r = mbase + mt * 16 + g;
                a[mt][0] = A[r * 36 + kb + t4];
                a[mt][1] = A[(r + 8) * 36 + kb + t4];
                a[mt][2] = A[r * 36 + kb + t4 + 4];
                a[mt][3] = A[(r + 8) * 36 + kb + t4 + 4];
            }
#pragma unroll
            for (int nt = 0; nt < 4; nt++) {
                int cn = (nt * 8 + g) * 36 + kb + t4;
                uint32_t b0 = B[cn], b1 = B[cn + 4];
                mma8(acc[0][nt], a[0], b0, b1);
                mma8(acc[1][nt], a[1], b0, b1);
            }
        }
        if (kk + 3 < NIT) { fill2(sb, toff, kk + 3, (kk + 3) & 3, tid); CP_COMMIT(); }
    }
    __syncthreads();

    // ---- k-half reduction via smem (reuse stage0 A region), P[128][34] ----
    float* P = (float*)dyn;
    if (kh == 1) {
#pragma unroll
        for (int mt = 0; mt < 2; mt++)
#pragma unroll
            for (int nt = 0; nt < 4; nt++) {
                int r = mbase + mt * 16 + g, c = nt * 8 + t4 * 2;
                *(float2*)&P[r * 34 + c]       = make_float2(acc[mt][nt][0], acc[mt][nt][1]);
                *(float2*)&P[(r + 8) * 34 + c] = make_float2(acc[mt][nt][2], acc[mt][nt][3]);
            }
    }
    __syncthreads();
    if (kh == 0) {
#pragma unroll
        for (int mt = 0; mt < 2; mt++)
#pragma unroll
            for (int nt = 0; nt < 4; nt++) {
                int r = mbase + mt * 16 + g, c = nt * 8 + t4 * 2;
                float2 p0 = *(float2*)&P[r * 34 + c];
                float2 p1 = *(float2*)&P[(r + 8) * 34 + c];
                acc[mt][nt][0] += p0.x; acc[mt][nt][1] += p0.y;
                acc[mt][nt][2] += p1.x; acc[mt][nt][3] += p1.y;
            }
        // ---- fused LN(32) + residual + GELU ----
#pragma unroll
        for (int mt = 0; mt < 2; mt++)
#pragma unroll
            for (int rr = 0; rr < 2; rr++) {
                float s = 0.f, q = 0.f;
#pragma unroll
                for (int nt = 0; nt < 4; nt++) {
                    float v0 = acc[mt][nt][rr * 2], v1 = acc[mt][nt][rr * 2 + 1];
                    s += v0 + v1; q += v0 * v0 + v1 * v1;
                }
                s += __shfl_xor_sync(0xffffffffu, s, 1);
                s += __shfl_xor_sync(0xffffffffu, s, 2);
                q += __shfl_xor_sync(0xffffffffu, q, 1);
                q += __shfl_xor_sync(0xffffffffu, q, 2);
                float mu = s * (1.0f / 32.0f);
                float rs = rsqrtf(q * (1.0f / 32.0f) - mu * mu + 1e-6f);
                int r = mbase + mt * 16 + rr * 8 + g;
                int nr = row0 + r;
                if (nr >= n) continue;
#pragma unroll
                for (int nt = 0; nt < 4; nt++) {
                    int c = nt * 8 + t4 * 2;
                    float2 xv = *(const float2*)(x + (size_t)nr * 32 + c);
                    float y0 = gelu_f((acc[mt][nt][rr * 2]     - mu) * rs * sg[c]     + sbe[c]     + xv.x);
                    float y1 = gelu_f((acc[mt][nt][rr * 2 + 1] - mu) * rs * sg[c + 1] + sbe[c + 1] + xv.y);
                    *(float2*)(out + (size_t)nr * 32 + c) = make_float2(y0, y1);
                }
            }
    }
}

// ---------------------------------------------------------------------------
extern "C" void kernel_launch(void* const* d_in, const int* in_sizes, int n_in,
                              void* d_out, int out_size) {
    const float* x   = (const float*)d_in[0];
    const int*   nid = (const int*)d_in[1];
    const void*  msk = (const void*)d_in[2];
    const float* Wc  = (const float*)d_in[3];
    const float* g0  = (const float*)d_in[4];
    const float* b0  = (const float*)d_in[5];
    const float* W1  = (const float*)d_in[6];
    const float* g1  = (const float*)d_in[7];
    const float* b1  = (const float*)d_in[8];
    const float* W2  = (const float*)d_in[9];
    const float* g2  = (const float*)d_in[10];
    const float* b2  = (const float*)d_in[11];
    float* out = (float*)d_out;
    int n = in_sizes[0] / 32;

    cudaFuncSetAttribute(k_conv1, cudaFuncAttributeMaxDynamicSharedMemorySize, T1_SMEM);
    cudaFuncSetAttribute(k_conv2, cudaFuncAttributeMaxDynamicSharedMemorySize, V2_SMEM);

    k_prep<<<(KK * 4096 + 255) / 256, 256>>>(W1, W2);
    k_conv0<<<(n + 7) / 8, 256>>>(x, Wc, g0, b0, (const unsigned char*)msk, n);
    int nb = (n + 127) / 128;
    k_conv1<<<nb, 256, T1_SMEM>>>(nid, msk, g1, b1, n);
    k_conv2<<<nb, 256, V2_SMEM>>>(x, nid, msk, g2, b2, out, n);
}